// round 13
// baseline (speedup 1.0000x reference)
#include <cuda_runtime.h>
#include <cuda_fp16.h>
#include <cstdint>

#define BB 16
#define NN 1024
#define INP 256
#define HEADS 8
#define DMH 32
#define INNER 256
#define OUP 256
#define NTBL 3969   // (2*32-1)^2
#define LOG2E 1.4426950408889634f
#define TBW 2208    // bias table window per CTA
#define HONES 0x3C003C00u

// ---------------- device scratch (allocation-free) ----------------
__device__ uint4 g_q[BB * HEADS * NN * DMH / 8];   // fp16, scale*log2e folded
__device__ uint4 g_k[BB * HEADS * NN * DMH / 8];   // fp16
__device__ uint4 g_v[BB * HEADS * NN * DMH / 8];   // fp16
__device__ uint32_t g_attn16[BB * NN * (INNER / 2)];  // fp16 pairs (b, n, d/2)
__device__ float g_tbl[HEADS * NTBL];              // [h][idx], pre-scaled by log2e

// ---------------- helpers ----------------
__device__ __forceinline__ uint32_t h2pack(float lo, float hi) {
    uint32_t r;
    asm("cvt.rn.f16x2.f32 %0, %1, %2;" : "=r"(r) : "f"(hi), "f"(lo));
    return r;
}

__device__ __forceinline__ uint32_t hexp2(uint32_t x) {
    uint32_t r;
    asm("ex2.approx.f16x2 %0, %1;" : "=r"(r) : "r"(x));
    return r;
}

__device__ __forceinline__ uint32_t prmt(uint32_t a, uint32_t b, uint32_t sel) {
    uint32_t d;
    asm("prmt.b32 %0, %1, %2, %3;" : "=r"(d) : "r"(a), "r"(b), "r"(sel));
    return d;
}

__device__ __forceinline__ void mma_f16(float c[4], const uint32_t a[4],
                                        uint32_t b0, uint32_t b1) {
    asm volatile(
        "mma.sync.aligned.m16n8k16.row.col.f32.f16.f16.f32 "
        "{%0,%1,%2,%3}, {%4,%5,%6,%7}, {%8,%9}, {%0,%1,%2,%3};"
        : "+f"(c[0]), "+f"(c[1]), "+f"(c[2]), "+f"(c[3])
        : "r"(a[0]), "r"(a[1]), "r"(a[2]), "r"(a[3]), "r"(b0), "r"(b1));
}

// ---------------- kernel 0: transpose bias table to [h][idx], fold log2e -----
__global__ __launch_bounds__(256) void tbl_kernel(const float* __restrict__ table) {
    int t = blockIdx.x * blockDim.x + threadIdx.x;
    if (t >= NTBL * HEADS) return;
    int idx = t >> 3, h = t & 7;
    g_tbl[h * NTBL + idx] = table[t] * LOG2E;
}

// ========= fp16 m16n8k16 GEMM core, 128x128 tile, K-step 32, double-buffered ==
// 256 threads = 8 warps: wm = wid&3 (32 rows), wn = wid>>2 (64 cols).
// A[m] k-pair words, pitch 20 (frag addr 20g+q distinct mod 32).
// B[kpair][n] words, pitch 136 (frag addr 8q+g distinct mod 32).

#define PAH 20
#define PBH 136

struct StageH {
    uint32_t Ah[128][PAH];   // 16 k-pair words + pad
    uint32_t Bh[16][PBH];    // 16 k-pairs x 128 cols
};

// ---------------- kernel 1: QKV GEMM (fp32 in, fp16 math, fp16 out) ----------
__global__ __launch_bounds__(256, 2) void qkv_tc(const float* __restrict__ A,
                                                 const float* __restrict__ W) {
    __shared__ StageH S[2];
    const int tid = threadIdx.x;
    const int lane = tid & 31, wid = tid >> 5;
    const int g = lane >> 2, q = lane & 3;
    const int wm = wid & 3, wn = wid >> 2;
    const int n0 = blockIdx.x * 128;
    const int m0 = blockIdx.y * 128;
    const int ldw = 768;

    const int ar = tid >> 1, ah_ = (tid & 1);     // A row, half (16 floats each)
    const int kb = tid >> 4, cw = (tid & 15) * 8; // B kpair, col

    float C[2][8][4] = {};
    float4 a4[4], be[2], bo[2];

    // load + store tile 0
#pragma unroll
    for (int i = 0; i < 4; i++)
        a4[i] = *(const float4*)&A[(size_t)(m0 + ar) * 256 + ah_ * 16 + i * 4];
    be[0] = *(const float4*)&W[(size_t)(2 * kb) * ldw + n0 + cw];
    be[1] = *(const float4*)&W[(size_t)(2 * kb) * ldw + n0 + cw + 4];
    bo[0] = *(const float4*)&W[(size_t)(2 * kb + 1) * ldw + n0 + cw];
    bo[1] = *(const float4*)&W[(size_t)(2 * kb + 1) * ldw + n0 + cw + 4];
    {
        uint4 w0 = make_uint4(h2pack(a4[0].x, a4[0].y), h2pack(a4[0].z, a4[0].w),
                              h2pack(a4[1].x, a4[1].y), h2pack(a4[1].z, a4[1].w));
        uint4 w1 = make_uint4(h2pack(a4[2].x, a4[2].y), h2pack(a4[2].z, a4[2].w),
                              h2pack(a4[3].x, a4[3].y), h2pack(a4[3].z, a4[3].w));
        *(uint4*)&S[0].Ah[ar][ah_ * 8] = w0;
        *(uint4*)&S[0].Ah[ar][ah_ * 8 + 4] = w1;
        uint4 b0 = make_uint4(h2pack(be[0].x, bo[0].x), h2pack(be[0].y, bo[0].y),
                              h2pack(be[0].z, bo[0].z), h2pack(be[0].w, bo[0].w));
        uint4 b1 = make_uint4(h2pack(be[1].x, bo[1].x), h2pack(be[1].y, bo[1].y),
                              h2pack(be[1].z, bo[1].z), h2pack(be[1].w, bo[1].w));
        *(uint4*)&S[0].Bh[kb][cw] = b0;
        *(uint4*)&S[0].Bh[kb][cw + 4] = b1;
    }
    // prefetch tile 1
#pragma unroll
    for (int i = 0; i < 4; i++)
        a4[i] = *(const float4*)&A[(size_t)(m0 + ar) * 256 + 32 + ah_ * 16 + i * 4];
    be[0] = *(const float4*)&W[(size_t)(32 + 2 * kb) * ldw + n0 + cw];
    be[1] = *(const float4*)&W[(size_t)(32 + 2 * kb) * ldw + n0 + cw + 4];
    bo[0] = *(const float4*)&W[(size_t)(32 + 2 * kb + 1) * ldw + n0 + cw];
    bo[1] = *(const float4*)&W[(size_t)(32 + 2 * kb + 1) * ldw + n0 + cw + 4];
    __syncthreads();

    for (int kt = 0; kt < 8; kt++) {
        const int cur = kt & 1;
        if (kt < 7) {
            uint4 w0 = make_uint4(h2pack(a4[0].x, a4[0].y), h2pack(a4[0].z, a4[0].w),
                                  h2pack(a4[1].x, a4[1].y), h2pack(a4[1].z, a4[1].w));
            uint4 w1 = make_uint4(h2pack(a4[2].x, a4[2].y), h2pack(a4[2].z, a4[2].w),
                                  h2pack(a4[3].x, a4[3].y), h2pack(a4[3].z, a4[3].w));
            *(uint4*)&S[cur ^ 1].Ah[ar][ah_ * 8] = w0;
            *(uint4*)&S[cur ^ 1].Ah[ar][ah_ * 8 + 4] = w1;
            uint4 b0 = make_uint4(h2pack(be[0].x, bo[0].x), h2pack(be[0].y, bo[0].y),
                                  h2pack(be[0].z, bo[0].z), h2pack(be[0].w, bo[0].w));
            uint4 b1 = make_uint4(h2pack(be[1].x, bo[1].x), h2pack(be[1].y, bo[1].y),
                                  h2pack(be[1].z, bo[1].z), h2pack(be[1].w, bo[1].w));
            *(uint4*)&S[cur ^ 1].Bh[kb][cw] = b0;
            *(uint4*)&S[cur ^ 1].Bh[kb][cw + 4] = b1;
        }
        if (kt < 6) {
            int k0 = (kt + 2) * 32;
#pragma unroll
            for (int i = 0; i < 4; i++)
                a4[i] = *(const float4*)&A[(size_t)(m0 + ar) * 256 + k0 + ah_ * 16 + i * 4];
            be[0] = *(const float4*)&W[(size_t)(k0 + 2 * kb) * ldw + n0 + cw];
            be[1] = *(const float4*)&W[(size_t)(k0 + 2 * kb) * ldw + n0 + cw + 4];
            bo[0] = *(const float4*)&W[(size_t)(k0 + 2 * kb + 1) * ldw + n0 + cw];
            bo[1] = *(const float4*)&W[(size_t)(k0 + 2 * kb + 1) * ldw + n0 + cw + 4];
        }
#pragma unroll
        for (int ks = 0; ks < 2; ks++) {
            uint32_t ah[2][4];
#pragma unroll
            for (int mf = 0; mf < 2; mf++) {
                int r = wm * 32 + mf * 16 + g;
                ah[mf][0] = S[cur].Ah[r][8 * ks + q];
                ah[mf][1] = S[cur].Ah[r + 8][8 * ks + q];
                ah[mf][2] = S[cur].Ah[r][8 * ks + q + 4];
                ah[mf][3] = S[cur].Ah[r + 8][8 * ks + q + 4];
            }
#pragma unroll
            for (int u = 0; u < 8; u++) {
                int col = wn * 64 + 8 * u + g;
                uint32_t b0 = S[cur].Bh[8 * ks + q][col];
                uint32_t b1 = S[cur].Bh[8 * ks + q + 4][col];
                mma_f16(C[0][u], ah[0], b0, b1);
                mma_f16(C[1][u], ah[1], b0, b1);
            }
        }
        __syncthreads();
    }

    const float qscale = 0.17677669529663687f * LOG2E;
    int b_ = m0 >> 10;
#pragma unroll
    for (int mf = 0; mf < 2; mf++) {
        int row = m0 + wm * 32 + mf * 16 + g;
        int n_ = row & 1023;
#pragma unroll
        for (int u = 0; u < 8; u++) {
            int col = n0 + wn * 64 + 8 * u + 2 * q;
            int seg = col >> 8;
            uint32_t* dst = (seg == 0) ? (uint32_t*)g_q
                          : ((seg == 1) ? (uint32_t*)g_k : (uint32_t*)g_v);
            int f = col & 255;
            int h = f >> 5, d = f & 31;
            size_t base = ((size_t)(b_ * HEADS + h) * NN + n_) * 16 + (d >> 1);
            float mul = (seg == 0) ? qscale : 1.0f;
            dst[base]       = h2pack(C[mf][u][0] * mul, C[mf][u][1] * mul);
            dst[base + 128] = h2pack(C[mf][u][2] * mul, C[mf][u][3] * mul);
        }
    }
}

// ---------------- kernel 3: output projection + bias (fp16 math) -------------
__global__ __launch_bounds__(256, 2) void out_tc(const float* __restrict__ W,
                                                 const float* __restrict__ bias,
                                                 float* __restrict__ out) {
    __shared__ StageH S[2];
    const int tid = threadIdx.x;
    const int lane = tid & 31, wid = tid >> 5;
    const int g = lane >> 2, q = lane & 3;
    const int wm = wid & 3, wn = wid >> 2;
    const int n0 = blockIdx.x * 128;
    const int m0 = blockIdx.y * 128;
    const int ldw = 256;

    const int ar = tid >> 1, ah_ = (tid & 1);
    const int kb = tid >> 4, cw = (tid & 15) * 8;
    const uint4* A16 = (const uint4*)g_attn16;    // 32 uint4 per 256-col row

    float C[2][8][4] = {};
    uint4 pa[2];
    float4 be[2], bo[2];

    pa[0] = A16[(size_t)(m0 + ar) * 32 + ah_ * 2];
    pa[1] = A16[(size_t)(m0 + ar) * 32 + ah_ * 2 + 1];
    be[0] = *(const float4*)&W[(size_t)(2 * kb) * ldw + n0 + cw];
    be[1] = *(const float4*)&W[(size_t)(2 * kb) * ldw + n0 + cw + 4];
    bo[0] = *(const float4*)&W[(size_t)(2 * kb + 1) * ldw + n0 + cw];
    bo[1] = *(const float4*)&W[(size_t)(2 * kb + 1) * ldw + n0 + cw + 4];
    {
        *(uint4*)&S[0].Ah[ar][ah_ * 8] = pa[0];
        *(uint4*)&S[0].Ah[ar][ah_ * 8 + 4] = pa[1];
        uint4 b0 = make_uint4(h2pack(be[0].x, bo[0].x), h2pack(be[0].y, bo[0].y),
                              h2pack(be[0].z, bo[0].z), h2pack(be[0].w, bo[0].w));
        uint4 b1 = make_uint4(h2pack(be[1].x, bo[1].x), h2pack(be[1].y, bo[1].y),
                              h2pack(be[1].z, bo[1].z), h2pack(be[1].w, bo[1].w));
        *(uint4*)&S[0].Bh[kb][cw] = b0;
        *(uint4*)&S[0].Bh[kb][cw + 4] = b1;
    }
    pa[0] = A16[(size_t)(m0 + ar) * 32 + 4 + ah_ * 2];
    pa[1] = A16[(size_t)(m0 + ar) * 32 + 4 + ah_ * 2 + 1];
    be[0] = *(const float4*)&W[(size_t)(32 + 2 * kb) * ldw + n0 + cw];
    be[1] = *(const float4*)&W[(size_t)(32 + 2 * kb) * ldw + n0 + cw + 4];
    bo[0] = *(const float4*)&W[(size_t)(32 + 2 * kb + 1) * ldw + n0 + cw];
    bo[1] = *(const float4*)&W[(size_t)(32 + 2 * kb + 1) * ldw + n0 + cw + 4];
    __syncthreads();

    for (int kt = 0; kt < 8; kt++) {
        const int cur = kt & 1;
        if (kt < 7) {
            *(uint4*)&S[cur ^ 1].Ah[ar][ah_ * 8] = pa[0];
            *(uint4*)&S[cur ^ 1].Ah[ar][ah_ * 8 + 4] = pa[1];
            uint4 b0 = make_uint4(h2pack(be[0].x, bo[0].x), h2pack(be[0].y, bo[0].y),
                                  h2pack(be[0].z, bo[0].z), h2pack(be[0].w, bo[0].w));
            uint4 b1 = make_uint4(h2pack(be[1].x, bo[1].x), h2pack(be[1].y, bo[1].y),
                                  h2pack(be[1].z, bo[1].z), h2pack(be[1].w, bo[1].w));
            *(uint4*)&S[cur ^ 1].Bh[kb][cw] = b0;
            *(uint4*)&S[cur ^ 1].Bh[kb][cw + 4] = b1;
        }
        if (kt < 6) {
            int k0 = (kt + 2) * 32;
            pa[0] = A16[(size_t)(m0 + ar) * 32 + (k0 >> 3) + ah_ * 2];
            pa[1] = A16[(size_t)(m0 + ar) * 32 + (k0 >> 3) + ah_ * 2 + 1];
            be[0] = *(const float4*)&W[(size_t)(k0 + 2 * kb) * ldw + n0 + cw];
            be[1] = *(const float4*)&W[(size_t)(k0 + 2 * kb) * ldw + n0 + cw + 4];
            bo[0] = *(const float4*)&W[(size_t)(k0 + 2 * kb + 1) * ldw + n0 + cw];
            bo[1] = *(const float4*)&W[(size_t)(k0 + 2 * kb + 1) * ldw + n0 + cw + 4];
        }
#pragma unroll
        for (int ks = 0; ks < 2; ks++) {
            uint32_t ah[2][4];
#pragma unroll
            for (int mf = 0; mf < 2; mf++) {
                int r = wm * 32 + mf * 16 + g;
                ah[mf][0] = S[cur].Ah[r][8 * ks + q];
                ah[mf][1] = S[cur].Ah[r + 8][8 * ks + q];
                ah[mf][2] = S[cur].Ah[r][8 * ks + q + 4];
                ah[mf][3] = S[cur].Ah[r + 8][8 * ks + q + 4];
            }
#pragma unroll
            for (int u = 0; u < 8; u++) {
                int col = wn * 64 + 8 * u + g;
                uint32_t b0 = S[cur].Bh[8 * ks + q][col];
                uint32_t b1 = S[cur].Bh[8 * ks + q + 4][col];
                mma_f16(C[0][u], ah[0], b0, b1);
                mma_f16(C[1][u], ah[1], b0, b1);
            }
        }
        __syncthreads();
    }

#pragma unroll
    for (int mf = 0; mf < 2; mf++) {
        int row = m0 + wm * 32 + mf * 16 + g;
#pragma unroll
        for (int u = 0; u < 8; u++) {
            int col = n0 + wn * 64 + 8 * u + 2 * q;
            float2 bv = *(const float2*)&bias[col];
            *(float2*)&out[(size_t)row * 256 + col] =
                make_float2(C[mf][u][0] + bv.x, C[mf][u][1] + bv.y);
            *(float2*)&out[(size_t)(row + 8) * 256 + col] =
                make_float2(C[mf][u][2] + bv.x, C[mf][u][3] + bv.y);
        }
    }
}

// ---------------- kernel 2: flash attention, fp16 everything -----------------
// fp16x2 exp (ex2.approx.f16x2); row-sums via ones-B mma (no shuffles at all).
__global__ __launch_bounds__(128) void attn_tc() {
    __shared__ uint32_t Qs[128][20];     // fp16x2 words: [row][d-pair]
    __shared__ uint32_t Ks[2][64][20];   // fp16x2 words: [col][d-pair]
    __shared__ uint32_t Vs[2][32][40];   // fp16x2 j-pairs: [jp][d]
    __shared__ float    Tb[TBW];         // bias table window

    const int tid = threadIdx.x;
    const int lane = tid & 31, wid = tid >> 5;
    const int g = lane >> 2, q = lane & 3;

    const int bh = blockIdx.y;
    const int h = bh & 7, b_ = bh >> 3;
    const int q0 = blockIdx.x * 128;

    const uint4* q4g = g_q + (size_t)bh * (NN * DMH / 8);
    const uint4* k4g = g_k + (size_t)bh * (NN * DMH / 8);
    const uint2* v2g = (const uint2*)(g_v + (size_t)bh * (NN * DMH / 8));
    const float* tbh = g_tbl + h * NTBL;

    const int base = ((q0 >> 5) + 31) * 63 + 31 - 1984;
    for (int j = tid; j < TBW; j += 128) {
        int idx = base + j;
        Tb[j] = tbh[idx < NTBL ? idx : NTBL - 1];
    }

#pragma unroll
    for (int i = 0; i < 4; i++) {
        int e = tid + i * 128;
        int r = e >> 2, c = e & 3;
        uint4 v = q4g[(q0 + r) * 4 + c];
        *(uint4*)&Qs[r][c * 4] = v;
    }

    const int kr = tid >> 2, kc = tid & 3;
    const int jp = tid >> 3, vc = tid & 7;

    uint4 kpre[2];
    uint2 vA[2], vB[2];
#pragma unroll
    for (int i = 0; i < 2; i++) {
        int r = kr + i * 32;
        uint4 kv = k4g[r * 4 + kc];
        *(uint4*)&Ks[0][r][kc * 4] = kv;
        int jj = jp + i * 16;
        uint2 a = v2g[(2 * jj) * 8 + vc];
        uint2 b = v2g[(2 * jj + 1) * 8 + vc];
        uint4 pw;
        pw.x = prmt(a.x, b.x, 0x5410u);
        pw.y = prmt(a.x, b.x, 0x7632u);
        pw.z = prmt(a.y, b.y, 0x5410u);
        pw.w = prmt(a.y, b.y, 0x7632u);
        *(uint4*)&Vs[0][jj][vc * 4] = pw;
    }
#pragma unroll
    for (int i = 0; i < 2; i++) {
        int r = 64 + kr + i * 32;
        kpre[i] = k4g[r * 4 + kc];
        int jj = 32 + jp + i * 16;
        vA[i] = v2g[(2 * jj) * 8 + vc];
        vB[i] = v2g[(2 * jj + 1) * 8 + vc];
    }
    __syncthreads();

    const int rb0 = wid * 32 + g;
    uint32_t qa[2][2][4];
#pragma unroll
    for (int mf = 0; mf < 2; mf++) {
        int row = rb0 + mf * 16;
#pragma unroll
        for (int ks = 0; ks < 2; ks++) {
            qa[mf][ks][0] = Qs[row][8 * ks + q];
            qa[mf][ks][1] = Qs[row + 8][8 * ks + q];
            qa[mf][ks][2] = Qs[row][8 * ks + q + 4];
            qa[mf][ks][3] = Qs[row + 8][8 * ks + q + 4];
        }
    }

    int CB[2][2];
#pragma unroll
    for (int mf = 0; mf < 2; mf++) {
        int i0 = q0 + wid * 32 + mf * 16 + g;
        int i1 = i0 + 8;
        CB[mf][0] = ((i0 >> 5) + 31) * 63 + (i0 & 31) + 31 - base;
        CB[mf][1] = ((i1 >> 5) + 31) * 63 + (i1 & 31) + 31 - base;
    }

    float O[2][4][4] = {};
    float Csum[2][4] = {};   // row-sum accumulators (ones-B mma)

    for (int kt = 0; kt < 16; kt++) {
        const int cur = kt & 1;
        __syncthreads();
        if (kt < 15) {
#pragma unroll
            for (int i = 0; i < 2; i++) {
                int r = kr + i * 32;
                *(uint4*)&Ks[cur ^ 1][r][kc * 4] = kpre[i];
                int jj = jp + i * 16;
                uint4 pw;
                pw.x = prmt(vA[i].x, vB[i].x, 0x5410u);
                pw.y = prmt(vA[i].x, vB[i].x, 0x7632u);
                pw.z = prmt(vA[i].y, vB[i].y, 0x5410u);
                pw.w = prmt(vA[i].y, vB[i].y, 0x7632u);
                *(uint4*)&Vs[cur ^ 1][jj][vc * 4] = pw;
            }
        }
        if (kt < 14) {
            int r0 = (kt + 2) * 64;
#pragma unroll
            for (int i = 0; i < 2; i++) {
                kpre[i] = k4g[(r0 + kr + i * 32) * 4 + kc];
                int jj = (kt + 2) * 32 + jp + i * 16;
                vA[i] = v2g[(2 * jj) * 8 + vc];
                vB[i] = v2g[(2 * jj + 1) * 8 + vc];
            }
        }
        const int k0 = kt * 64;

        // ---- S = bias ----
        float s[2][8][4];
#pragma unroll
        for (int mf = 0; mf < 2; mf++)
#pragma unroll
            for (int t = 0; t < 8; t++) {
                int colb = k0 + 8 * t + 2 * q;
                int off = 63 * (colb >> 5) + (colb & 31);
                s[mf][t][0] = Tb[CB[mf][0] - off];
                s[mf][t][1] = Tb[CB[mf][0] - off - 1];
                s[mf][t][2] = Tb[CB[mf][1] - off];
                s[mf][t][3] = Tb[CB[mf][1] - off - 1];
            }

        // ---- S += Q K^T ----
#pragma unroll
        for (int t = 0; t < 8; t++) {
#pragma unroll
            for (int ks = 0; ks < 2; ks++) {
                uint32_t b0 = Ks[cur][8 * t + g][8 * ks + q];
                uint32_t b1 = Ks[cur][8 * t + g][8 * ks + q + 4];
                mma_f16(s[0][t], qa[0][ks], b0, b1);
                mma_f16(s[1][t], qa[1][ks], b0, b1);
            }
        }

        // ---- pack to fp16 pairs, exp2 in fp16x2 ----
        uint32_t ph[2][8][2];
#pragma unroll
        for (int mf = 0; mf < 2; mf++)
#pragma unroll
            for (int t = 0; t < 8; t++) {
                ph[mf][t][0] = hexp2(h2pack(s[mf][t][0], s[mf][t][1]));
                ph[mf][t][1] = hexp2(h2pack(s[mf][t][2], s[mf][t][3]));
            }

        // ---- O += P V ; row-sums += P * ones (one extra mma per ks/mf) ----
#pragma unroll
        for (int ks = 0; ks < 4; ks++) {
            uint32_t pa[2][4];
#pragma unroll
            for (int mf = 0; mf < 2; mf++) {
                pa[mf][0] = ph[mf][2 * ks][0];
                pa[mf][1] = ph[mf][2 * ks][1];
                pa[mf][2] = ph[mf][2 * ks + 1][0];
                pa[mf][3] = ph[mf][2 * ks + 1][1];
            }
#pragma unroll
            for (int u = 0; u < 4; u++) {
                uint32_t b0 = Vs[cur][8 * ks + q][8 * u + g];
                uint32_t b1 = Vs[cur][8 * ks + q + 4][8 * u + g];
                mma_f16(O[0][u], pa[0], b0, b1);
                mma_f16(O[1][u], pa[1], b0, b1);
            }
            mma_f16(Csum[0], pa[0], HONES, HONES);
            mma_f16(Csum[1], pa[1], HONES, HONES);
        }
    }

    // ---- epilogue: l already fully reduced by ones-mma; normalize, write ----
#pragma unroll
    for (int mf = 0; mf < 2; mf++) {
        float inv0 = 1.0f / Csum[mf][0];
        float inv1 = 1.0f / Csum[mf][2];
        int orow = q0 + wid * 32 + mf * 16 + g;
#pragma unroll
        for (int u = 0; u < 4; u++) {
            int dw = h * 16 + 4 * u + q;
            g_attn16[((size_t)b_ * NN + orow) * 128 + dw] =
                h2pack(O[mf][u][0] * inv0, O[mf][u][1] * inv0);
            g_attn16[((size_t)b_ * NN + orow + 8) * 128 + dw] =
                h2pack(O[mf][u][2] * inv1, O[mf][u][3] * inv1);
        }
    }
}

// ---------------- launch ----------------
extern "C" void kernel_launch(void* const* d_in, const int* in_sizes, int n_in,
                              void* d_out, int out_size) {
    const float* x      = (const float*)d_in[0];
    const float* w_qkv  = (const float*)d_in[1];
    const float* w_out  = (const float*)d_in[2];
    const float* b_out  = (const float*)d_in[3];
    const float* table  = (const float*)d_in[4];
    float* out = (float*)d_out;

    tbl_kernel<<<(NTBL * HEADS + 255) / 256, 256>>>(table);
    qkv_tc<<<dim3(768 / 128, (BB * NN) / 128), 256>>>(x, w_qkv);
    attn_tc<<<dim3(NN / 128, BB * HEADS), 128>>>();
    out_tc<<<dim3(256 / 128, (BB * NN) / 128), 256>>>(w_out, b_out, out);
}

// round 14
// speedup vs baseline: 1.6350x; 1.6350x over previous
#include <cuda_runtime.h>
#include <cuda_fp16.h>
#include <cstdint>

#define BB 16
#define NN 1024
#define INP 256
#define HEADS 8
#define DMH 32
#define INNER 256
#define OUP 256
#define NTBL 3969   // (2*32-1)^2
#define LOG2E 1.4426950408889634f
#define TBW 2208    // bias table window per CTA
#define HONES 0x3C003C00u

// ---------------- device scratch (allocation-free) ----------------
__device__ uint4 g_q[BB * HEADS * NN * DMH / 8];   // fp16, scale*log2e folded
__device__ uint4 g_k[BB * HEADS * NN * DMH / 8];   // fp16
__device__ uint4 g_v[BB * HEADS * NN * DMH / 8];   // fp16
__device__ uint32_t g_attn16[BB * NN * (INNER / 2)];  // fp16 pairs (b, n, d/2)
__device__ float g_tbl[HEADS * NTBL];              // [h][idx], pre-scaled by log2e

// ---------------- helpers ----------------
__device__ __forceinline__ uint32_t h2pack(float lo, float hi) {
    uint32_t r;
    asm("cvt.rn.f16x2.f32 %0, %1, %2;" : "=r"(r) : "f"(hi), "f"(lo));
    return r;
}

__device__ __forceinline__ uint32_t hexp2(uint32_t x) {
    uint32_t r;
    asm("ex2.approx.f16x2 %0, %1;" : "=r"(r) : "r"(x));
    return r;
}

__device__ __forceinline__ uint32_t prmt(uint32_t a, uint32_t b, uint32_t sel) {
    uint32_t d;
    asm("prmt.b32 %0, %1, %2, %3;" : "=r"(d) : "r"(a), "r"(b), "r"(sel));
    return d;
}

__device__ __forceinline__ void mma_f16(float c[4], const uint32_t a[4],
                                        uint32_t b0, uint32_t b1) {
    asm volatile(
        "mma.sync.aligned.m16n8k16.row.col.f32.f16.f16.f32 "
        "{%0,%1,%2,%3}, {%4,%5,%6,%7}, {%8,%9}, {%0,%1,%2,%3};"
        : "+f"(c[0]), "+f"(c[1]), "+f"(c[2]), "+f"(c[3])
        : "r"(a[0]), "r"(a[1]), "r"(a[2]), "r"(a[3]), "r"(b0), "r"(b1));
}

// ---------------- kernel 0: transpose bias table to [h][idx], fold log2e -----
__global__ __launch_bounds__(256) void tbl_kernel(const float* __restrict__ table) {
    int t = blockIdx.x * blockDim.x + threadIdx.x;
    if (t >= NTBL * HEADS) return;
    int idx = t >> 3, h = t & 7;
    g_tbl[h * NTBL + idx] = table[t] * LOG2E;
}

// ========= fp16 m16n8k16 tensor GEMM core, 128x128 tile, K-step 16 ============
// (exact R12 geometry: the K-step-32 variant regressed via register pressure)
#define PAH 12
#define PBH 136

struct StageH {
    uint32_t Ah[128][PAH];
    uint32_t Bh[8][PBH];
};

// ---------------- kernel 1: QKV GEMM (fp32 in, fp16 math, fp16 out) ----------
__global__ __launch_bounds__(256, 2) void qkv_tc(const float* __restrict__ A,
                                                 const float* __restrict__ W) {
    __shared__ StageH S[2];
    const int tid = threadIdx.x;
    const int lane = tid & 31, wid = tid >> 5;
    const int g = lane >> 2, q = lane & 3;
    const int wm = wid & 3, wn = wid >> 2;
    const int n0 = blockIdx.x * 128;
    const int m0 = blockIdx.y * 128;
    const int ldw = 768;

    const int ar0 = tid >> 2, ac0 = (tid & 3) * 4;   // A rows 0..63, float chunk
    const int ar1 = ar0 + 64;
    const int acw = (tid & 3) * 2;                   // word offset in row
    const int kb = tid >> 5, cw = (tid & 31) * 4;    // B kpair row, col

    float C[2][8][4] = {};
    float4 pa0, pa1, pe, po;

    pa0 = *(const float4*)&A[(size_t)(m0 + ar0) * 256 + ac0];
    pa1 = *(const float4*)&A[(size_t)(m0 + ar1) * 256 + ac0];
    pe  = *(const float4*)&W[(size_t)(2 * kb) * ldw + n0 + cw];
    po  = *(const float4*)&W[(size_t)(2 * kb + 1) * ldw + n0 + cw];
    {
        uint2 a0 = make_uint2(h2pack(pa0.x, pa0.y), h2pack(pa0.z, pa0.w));
        uint2 a1 = make_uint2(h2pack(pa1.x, pa1.y), h2pack(pa1.z, pa1.w));
        uint4 bw = make_uint4(h2pack(pe.x, po.x), h2pack(pe.y, po.y),
                              h2pack(pe.z, po.z), h2pack(pe.w, po.w));
        *(uint2*)&S[0].Ah[ar0][acw] = a0;
        *(uint2*)&S[0].Ah[ar1][acw] = a1;
        *(uint4*)&S[0].Bh[kb][cw] = bw;
    }
    pa0 = *(const float4*)&A[(size_t)(m0 + ar0) * 256 + 16 + ac0];
    pa1 = *(const float4*)&A[(size_t)(m0 + ar1) * 256 + 16 + ac0];
    pe  = *(const float4*)&W[(size_t)(16 + 2 * kb) * ldw + n0 + cw];
    po  = *(const float4*)&W[(size_t)(16 + 2 * kb + 1) * ldw + n0 + cw];
    __syncthreads();

    for (int kt = 0; kt < 16; kt++) {
        const int cur = kt & 1;
        if (kt < 15) {
            uint2 a0 = make_uint2(h2pack(pa0.x, pa0.y), h2pack(pa0.z, pa0.w));
            uint2 a1 = make_uint2(h2pack(pa1.x, pa1.y), h2pack(pa1.z, pa1.w));
            uint4 bw = make_uint4(h2pack(pe.x, po.x), h2pack(pe.y, po.y),
                                  h2pack(pe.z, po.z), h2pack(pe.w, po.w));
            *(uint2*)&S[cur ^ 1].Ah[ar0][acw] = a0;
            *(uint2*)&S[cur ^ 1].Ah[ar1][acw] = a1;
            *(uint4*)&S[cur ^ 1].Bh[kb][cw] = bw;
        }
        if (kt < 14) {
            int k0 = (kt + 2) * 16;
            pa0 = *(const float4*)&A[(size_t)(m0 + ar0) * 256 + k0 + ac0];
            pa1 = *(const float4*)&A[(size_t)(m0 + ar1) * 256 + k0 + ac0];
            pe  = *(const float4*)&W[(size_t)(k0 + 2 * kb) * ldw + n0 + cw];
            po  = *(const float4*)&W[(size_t)(k0 + 2 * kb + 1) * ldw + n0 + cw];
        }
        uint32_t ah[2][4];
#pragma unroll
        for (int mf = 0; mf < 2; mf++) {
            int r = wm * 32 + mf * 16 + g;
            ah[mf][0] = S[cur].Ah[r][q];
            ah[mf][1] = S[cur].Ah[r + 8][q];
            ah[mf][2] = S[cur].Ah[r][q + 4];
            ah[mf][3] = S[cur].Ah[r + 8][q + 4];
        }
#pragma unroll
        for (int u = 0; u < 8; u++) {
            int col = wn * 64 + 8 * u + g;
            uint32_t b0 = S[cur].Bh[q][col];
            uint32_t b1 = S[cur].Bh[q + 4][col];
            mma_f16(C[0][u], ah[0], b0, b1);
            mma_f16(C[1][u], ah[1], b0, b1);
        }
        __syncthreads();
    }

    const float qscale = 0.17677669529663687f * LOG2E;
    int b_ = m0 >> 10;
#pragma unroll
    for (int mf = 0; mf < 2; mf++) {
        int row = m0 + wm * 32 + mf * 16 + g;
        int n_ = row & 1023;
#pragma unroll
        for (int u = 0; u < 8; u++) {
            int col = n0 + wn * 64 + 8 * u + 2 * q;
            int seg = col >> 8;
            uint32_t* dst = (seg == 0) ? (uint32_t*)g_q
                          : ((seg == 1) ? (uint32_t*)g_k : (uint32_t*)g_v);
            int f = col & 255;
            int h = f >> 5, d = f & 31;
            size_t base = ((size_t)(b_ * HEADS + h) * NN + n_) * 16 + (d >> 1);
            float mul = (seg == 0) ? qscale : 1.0f;
            dst[base]       = h2pack(C[mf][u][0] * mul, C[mf][u][1] * mul);
            dst[base + 128] = h2pack(C[mf][u][2] * mul, C[mf][u][3] * mul);
        }
    }
}

// ---------------- kernel 3: output projection + bias (fp16 math) -------------
__global__ __launch_bounds__(256, 2) void out_tc(const float* __restrict__ W,
                                                 const float* __restrict__ bias,
                                                 float* __restrict__ out) {
    __shared__ StageH S[2];
    const int tid = threadIdx.x;
    const int lane = tid & 31, wid = tid >> 5;
    const int g = lane >> 2, q = lane & 3;
    const int wm = wid & 3, wn = wid >> 2;
    const int n0 = blockIdx.x * 128;
    const int m0 = blockIdx.y * 128;
    const int ldw = 256;

    const int ar = tid >> 1, cw4 = (tid & 1) * 4;
    const int kb = tid >> 5, cw = (tid & 31) * 4;
    const uint4* A16 = (const uint4*)g_attn16;

    float C[2][8][4] = {};
    uint4 pa;
    float4 pe, po;

    pa = A16[(size_t)(m0 + ar) * 32 + (cw4 >> 2)];
    pe = *(const float4*)&W[(size_t)(2 * kb) * ldw + n0 + cw];
    po = *(const float4*)&W[(size_t)(2 * kb + 1) * ldw + n0 + cw];
    {
        uint4 bw = make_uint4(h2pack(pe.x, po.x), h2pack(pe.y, po.y),
                              h2pack(pe.z, po.z), h2pack(pe.w, po.w));
        *(uint4*)&S[0].Ah[ar][cw4] = pa;
        *(uint4*)&S[0].Bh[kb][cw] = bw;
    }
    pa = A16[(size_t)(m0 + ar) * 32 + 2 + (cw4 >> 2)];
    pe = *(const float4*)&W[(size_t)(16 + 2 * kb) * ldw + n0 + cw];
    po = *(const float4*)&W[(size_t)(16 + 2 * kb + 1) * ldw + n0 + cw];
    __syncthreads();

    for (int kt = 0; kt < 16; kt++) {
        const int cur = kt & 1;
        if (kt < 15) {
            uint4 bw = make_uint4(h2pack(pe.x, po.x), h2pack(pe.y, po.y),
                                  h2pack(pe.z, po.z), h2pack(pe.w, po.w));
            *(uint4*)&S[cur ^ 1].Ah[ar][cw4] = pa;
            *(uint4*)&S[cur ^ 1].Bh[kb][cw] = bw;
        }
        if (kt < 14) {
            int k0 = (kt + 2) * 16;
            pa = A16[(size_t)(m0 + ar) * 32 + (k0 >> 3) + (cw4 >> 2)];
            pe = *(const float4*)&W[(size_t)(k0 + 2 * kb) * ldw + n0 + cw];
            po = *(const float4*)&W[(size_t)(k0 + 2 * kb + 1) * ldw + n0 + cw];
        }
        uint32_t ah[2][4];
#pragma unroll
        for (int mf = 0; mf < 2; mf++) {
            int r = wm * 32 + mf * 16 + g;
            ah[mf][0] = S[cur].Ah[r][q];
            ah[mf][1] = S[cur].Ah[r + 8][q];
            ah[mf][2] = S[cur].Ah[r][q + 4];
            ah[mf][3] = S[cur].Ah[r + 8][q + 4];
        }
#pragma unroll
        for (int u = 0; u < 8; u++) {
            int col = wn * 64 + 8 * u + g;
            uint32_t b0 = S[cur].Bh[q][col];
            uint32_t b1 = S[cur].Bh[q + 4][col];
            mma_f16(C[0][u], ah[0], b0, b1);
            mma_f16(C[1][u], ah[1], b0, b1);
        }
        __syncthreads();
    }

#pragma unroll
    for (int mf = 0; mf < 2; mf++) {
        int row = m0 + wm * 32 + mf * 16 + g;
#pragma unroll
        for (int u = 0; u < 8; u++) {
            int col = n0 + wn * 64 + 8 * u + 2 * q;
            float2 bv = *(const float2*)&bias[col];
            *(float2*)&out[(size_t)row * 256 + col] =
                make_float2(C[mf][u][0] + bv.x, C[mf][u][1] + bv.y);
            *(float2*)&out[(size_t)(row + 8) * 256 + col] =
                make_float2(C[mf][u][2] + bv.x, C[mf][u][3] + bv.y);
        }
    }
}

// ---------------- kernel 2: flash attention, fp16 everything -----------------
// fp16x2 exp (ex2.approx.f16x2); row-sums via ones-B mma (no shuffles at all).
__global__ __launch_bounds__(128) void attn_tc() {
    __shared__ uint32_t Qs[128][20];     // fp16x2 words: [row][d-pair]
    __shared__ uint32_t Ks[2][64][20];   // fp16x2 words: [col][d-pair]
    __shared__ uint32_t Vs[2][32][40];   // fp16x2 j-pairs: [jp][d]
    __shared__ float    Tb[TBW];         // bias table window

    const int tid = threadIdx.x;
    const int lane = tid & 31, wid = tid >> 5;
    const int g = lane >> 2, q = lane & 3;

    const int bh = blockIdx.y;
    const int h = bh & 7, b_ = bh >> 3;
    const int q0 = blockIdx.x * 128;

    const uint4* q4g = g_q + (size_t)bh * (NN * DMH / 8);
    const uint4* k4g = g_k + (size_t)bh * (NN * DMH / 8);
    const uint2* v2g = (const uint2*)(g_v + (size_t)bh * (NN * DMH / 8));
    const float* tbh = g_tbl + h * NTBL;

    const int base = ((q0 >> 5) + 31) * 63 + 31 - 1984;
    for (int j = tid; j < TBW; j += 128) {
        int idx = base + j;
        Tb[j] = tbh[idx < NTBL ? idx : NTBL - 1];
    }

#pragma unroll
    for (int i = 0; i < 4; i++) {
        int e = tid + i * 128;
        int r = e >> 2, c = e & 3;
        uint4 v = q4g[(q0 + r) * 4 + c];
        *(uint4*)&Qs[r][c * 4] = v;
    }

    const int kr = tid >> 2, kc = tid & 3;
    const int jp = tid >> 3, vc = tid & 7;

    uint4 kpre[2];
    uint2 vA[2], vB[2];
#pragma unroll
    for (int i = 0; i < 2; i++) {
        int r = kr + i * 32;
        uint4 kv = k4g[r * 4 + kc];
        *(uint4*)&Ks[0][r][kc * 4] = kv;
        int jj = jp + i * 16;
        uint2 a = v2g[(2 * jj) * 8 + vc];
        uint2 b = v2g[(2 * jj + 1) * 8 + vc];
        uint4 pw;
        pw.x = prmt(a.x, b.x, 0x5410u);
        pw.y = prmt(a.x, b.x, 0x7632u);
        pw.z = prmt(a.y, b.y, 0x5410u);
        pw.w = prmt(a.y, b.y, 0x7632u);
        *(uint4*)&Vs[0][jj][vc * 4] = pw;
    }
#pragma unroll
    for (int i = 0; i < 2; i++) {
        int r = 64 + kr + i * 32;
        kpre[i] = k4g[r * 4 + kc];
        int jj = 32 + jp + i * 16;
        vA[i] = v2g[(2 * jj) * 8 + vc];
        vB[i] = v2g[(2 * jj + 1) * 8 + vc];
    }
    __syncthreads();

    const int rb0 = wid * 32 + g;
    uint32_t qa[2][2][4];
#pragma unroll
    for (int mf = 0; mf < 2; mf++) {
        int row = rb0 + mf * 16;
#pragma unroll
        for (int ks = 0; ks < 2; ks++) {
            qa[mf][ks][0] = Qs[row][8 * ks + q];
            qa[mf][ks][1] = Qs[row + 8][8 * ks + q];
            qa[mf][ks][2] = Qs[row][8 * ks + q + 4];
            qa[mf][ks][3] = Qs[row + 8][8 * ks + q + 4];
        }
    }

    int CB[2][2];
#pragma unroll
    for (int mf = 0; mf < 2; mf++) {
        int i0 = q0 + wid * 32 + mf * 16 + g;
        int i1 = i0 + 8;
        CB[mf][0] = ((i0 >> 5) + 31) * 63 + (i0 & 31) + 31 - base;
        CB[mf][1] = ((i1 >> 5) + 31) * 63 + (i1 & 31) + 31 - base;
    }

    float O[2][4][4] = {};
    float Csum[2][4] = {};   // row-sum accumulators (ones-B mma)

    for (int kt = 0; kt < 16; kt++) {
        const int cur = kt & 1;
        __syncthreads();
        if (kt < 15) {
#pragma unroll
            for (int i = 0; i < 2; i++) {
                int r = kr + i * 32;
                *(uint4*)&Ks[cur ^ 1][r][kc * 4] = kpre[i];
                int jj = jp + i * 16;
                uint4 pw;
                pw.x = prmt(vA[i].x, vB[i].x, 0x5410u);
                pw.y = prmt(vA[i].x, vB[i].x, 0x7632u);
                pw.z = prmt(vA[i].y, vB[i].y, 0x5410u);
                pw.w = prmt(vA[i].y, vB[i].y, 0x7632u);
                *(uint4*)&Vs[cur ^ 1][jj][vc * 4] = pw;
            }
        }
        if (kt < 14) {
            int r0 = (kt + 2) * 64;
#pragma unroll
            for (int i = 0; i < 2; i++) {
                kpre[i] = k4g[(r0 + kr + i * 32) * 4 + kc];
                int jj = (kt + 2) * 32 + jp + i * 16;
                vA[i] = v2g[(2 * jj) * 8 + vc];
                vB[i] = v2g[(2 * jj + 1) * 8 + vc];
            }
        }
        const int k0 = kt * 64;

        // ---- S = bias ----
        float s[2][8][4];
#pragma unroll
        for (int mf = 0; mf < 2; mf++)
#pragma unroll
            for (int t = 0; t < 8; t++) {
                int colb = k0 + 8 * t + 2 * q;
                int off = 63 * (colb >> 5) + (colb & 31);
                s[mf][t][0] = Tb[CB[mf][0] - off];
                s[mf][t][1] = Tb[CB[mf][0] - off - 1];
                s[mf][t][2] = Tb[CB[mf][1] - off];
                s[mf][t][3] = Tb[CB[mf][1] - off - 1];
            }

        // ---- S += Q K^T ----
#pragma unroll
        for (int t = 0; t < 8; t++) {
#pragma unroll
            for (int ks = 0; ks < 2; ks++) {
                uint32_t b0 = Ks[cur][8 * t + g][8 * ks + q];
                uint32_t b1 = Ks[cur][8 * t + g][8 * ks + q + 4];
                mma_f16(s[0][t], qa[0][ks], b0, b1);
                mma_f16(s[1][t], qa[1][ks], b0, b1);
            }
        }

        // ---- pack to fp16 pairs, exp2 in fp16x2 ----
        uint32_t ph[2][8][2];
#pragma unroll
        for (int mf = 0; mf < 2; mf++)
#pragma unroll
            for (int t = 0; t < 8; t++) {
                ph[mf][t][0] = hexp2(h2pack(s[mf][t][0], s[mf][t][1]));
                ph[mf][t][1] = hexp2(h2pack(s[mf][t][2], s[mf][t][3]));
            }

        // ---- O += P V ; row-sums += P * ones ----
#pragma unroll
        for (int ks = 0; ks < 4; ks++) {
            uint32_t pa[2][4];
#pragma unroll
            for (int mf = 0; mf < 2; mf++) {
                pa[mf][0] = ph[mf][2 * ks][0];
                pa[mf][1] = ph[mf][2 * ks][1];
                pa[mf][2] = ph[mf][2 * ks + 1][0];
                pa[mf][3] = ph[mf][2 * ks + 1][1];
            }
#pragma unroll
            for (int u = 0; u < 4; u++) {
                uint32_t b0 = Vs[cur][8 * ks + q][8 * u + g];
                uint32_t b1 = Vs[cur][8 * ks + q + 4][8 * u + g];
                mma_f16(O[0][u], pa[0], b0, b1);
                mma_f16(O[1][u], pa[1], b0, b1);
            }
            mma_f16(Csum[0], pa[0], HONES, HONES);
            mma_f16(Csum[1], pa[1], HONES, HONES);
        }
    }

    // ---- epilogue: l fully reduced by ones-mma; normalize, write fp16 ----
#pragma unroll
    for (int mf = 0; mf < 2; mf++) {
        float inv0 = 1.0f / Csum[mf][0];
        float inv1 = 1.0f / Csum[mf][2];
        int orow = q0 + wid * 32 + mf * 16 + g;
#pragma unroll
        for (int u = 0; u < 4; u++) {
            int dw = h * 16 + 4 * u + q;
            g_attn16[((size_t)b_ * NN + orow) * 128 + dw] =
                h2pack(O[mf][u][0] * inv0, O[mf][u][1] * inv0);
            g_attn16[((size_t)b_ * NN + orow + 8) * 128 + dw] =
                h2pack(O[mf][u][2] * inv1, O[mf][u][3] * inv1);
        }
    }
}

// ---------------- launch ----------------
extern "C" void kernel_launch(void* const* d_in, const int* in_sizes, int n_in,
                              void* d_out, int out_size) {
    const float* x      = (const float*)d_in[0];
    const float* w_qkv  = (const float*)d_in[1];
    const float* w_out  = (const float*)d_in[2];
    const float* b_out  = (const float*)d_in[3];
    const float* table  = (const float*)d_in[4];
    float* out = (float*)d_out;

    tbl_kernel<<<(NTBL * HEADS + 255) / 256, 256>>>(table);
    qkv_tc<<<dim3(768 / 128, (BB * NN) / 128), 256>>>(x, w_qkv);
    attn_tc<<<dim3(NN / 128, BB * HEADS), 128>>>();
    out_tc<<<dim3(256 / 128, (BB * NN) / 128), 256>>>(w_out, b_out, out);
}

// round 15
// speedup vs baseline: 1.6484x; 1.0082x over previous
#include <cuda_runtime.h>
#include <cuda_fp16.h>
#include <cstdint>

#define BB 16
#define NN 1024
#define INP 256
#define HEADS 8
#define DMH 32
#define INNER 256
#define OUP 256
#define NTBL 3969   // (2*32-1)^2
#define LOG2E 1.4426950408889634f
#define TBW 2208    // bias table window per CTA
#define HONES 0x3C003C00u

// ---------------- device scratch (allocation-free) ----------------
__device__ uint4 g_q[BB * HEADS * NN * DMH / 8];   // fp16, scale*log2e folded
__device__ uint4 g_k[BB * HEADS * NN * DMH / 8];   // fp16
__device__ uint4 g_v[BB * HEADS * NN * DMH / 8];   // fp16
__device__ uint32_t g_attn16[BB * NN * (INNER / 2)];  // fp16 pairs (b, n, d/2)
__device__ float g_tbl[HEADS * NTBL];              // [h][idx], pre-scaled by log2e

// ---------------- helpers ----------------
__device__ __forceinline__ uint32_t h2pack(float lo, float hi) {
    uint32_t r;
    asm("cvt.rn.f16x2.f32 %0, %1, %2;" : "=r"(r) : "f"(hi), "f"(lo));
    return r;
}

__device__ __forceinline__ uint32_t hexp2(uint32_t x) {
    uint32_t r;
    asm("ex2.approx.f16x2 %0, %1;" : "=r"(r) : "r"(x));
    return r;
}

__device__ __forceinline__ uint32_t prmt(uint32_t a, uint32_t b, uint32_t sel) {
    uint32_t d;
    asm("prmt.b32 %0, %1, %2, %3;" : "=r"(d) : "r"(a), "r"(b), "r"(sel));
    return d;
}

__device__ __forceinline__ void mma_f16(float c[4], const uint32_t a[4],
                                        uint32_t b0, uint32_t b1) {
    asm volatile(
        "mma.sync.aligned.m16n8k16.row.col.f32.f16.f16.f32 "
        "{%0,%1,%2,%3}, {%4,%5,%6,%7}, {%8,%9}, {%0,%1,%2,%3};"
        : "+f"(c[0]), "+f"(c[1]), "+f"(c[2]), "+f"(c[3])
        : "r"(a[0]), "r"(a[1]), "r"(a[2]), "r"(a[3]), "r"(b0), "r"(b1));
}

// ---------------- kernel 0: transpose bias table to [h][idx], fold log2e -----
__global__ __launch_bounds__(256) void tbl_kernel(const float* __restrict__ table) {
    int t = blockIdx.x * blockDim.x + threadIdx.x;
    if (t >= NTBL * HEADS) return;
    int idx = t >> 3, h = t & 7;
    g_tbl[h * NTBL + idx] = table[t] * LOG2E;
}

// ========= fp16 m16n8k16 tensor GEMM core, 128x128 tile, K-step 16 ============
// (exact R12 geometry: the K-step-32 variant regressed via register pressure)
#define PAH 12
#define PBH 136

struct StageH {
    uint32_t Ah[128][PAH];
    uint32_t Bh[8][PBH];
};

// ---------------- kernel 1: QKV GEMM (fp32 in, fp16 math, fp16 out) ----------
__global__ __launch_bounds__(256, 2) void qkv_tc(const float* __restrict__ A,
                                                 const float* __restrict__ W) {
    __shared__ StageH S[2];
    const int tid = threadIdx.x;
    const int lane = tid & 31, wid = tid >> 5;
    const int g = lane >> 2, q = lane & 3;
    const int wm = wid & 3, wn = wid >> 2;
    const int n0 = blockIdx.x * 128;
    const int m0 = blockIdx.y * 128;
    const int ldw = 768;

    const int ar0 = tid >> 2, ac0 = (tid & 3) * 4;   // A rows 0..63, float chunk
    const int ar1 = ar0 + 64;
    const int acw = (tid & 3) * 2;                   // word offset in row
    const int kb = tid >> 5, cw = (tid & 31) * 4;    // B kpair row, col

    float C[2][8][4] = {};
    float4 pa0, pa1, pe, po;

    pa0 = *(const float4*)&A[(size_t)(m0 + ar0) * 256 + ac0];
    pa1 = *(const float4*)&A[(size_t)(m0 + ar1) * 256 + ac0];
    pe  = *(const float4*)&W[(size_t)(2 * kb) * ldw + n0 + cw];
    po  = *(const float4*)&W[(size_t)(2 * kb + 1) * ldw + n0 + cw];
    {
        uint2 a0 = make_uint2(h2pack(pa0.x, pa0.y), h2pack(pa0.z, pa0.w));
        uint2 a1 = make_uint2(h2pack(pa1.x, pa1.y), h2pack(pa1.z, pa1.w));
        uint4 bw = make_uint4(h2pack(pe.x, po.x), h2pack(pe.y, po.y),
                              h2pack(pe.z, po.z), h2pack(pe.w, po.w));
        *(uint2*)&S[0].Ah[ar0][acw] = a0;
        *(uint2*)&S[0].Ah[ar1][acw] = a1;
        *(uint4*)&S[0].Bh[kb][cw] = bw;
    }
    pa0 = *(const float4*)&A[(size_t)(m0 + ar0) * 256 + 16 + ac0];
    pa1 = *(const float4*)&A[(size_t)(m0 + ar1) * 256 + 16 + ac0];
    pe  = *(const float4*)&W[(size_t)(16 + 2 * kb) * ldw + n0 + cw];
    po  = *(const float4*)&W[(size_t)(16 + 2 * kb + 1) * ldw + n0 + cw];
    __syncthreads();

    for (int kt = 0; kt < 16; kt++) {
        const int cur = kt & 1;
        if (kt < 15) {
            uint2 a0 = make_uint2(h2pack(pa0.x, pa0.y), h2pack(pa0.z, pa0.w));
            uint2 a1 = make_uint2(h2pack(pa1.x, pa1.y), h2pack(pa1.z, pa1.w));
            uint4 bw = make_uint4(h2pack(pe.x, po.x), h2pack(pe.y, po.y),
                                  h2pack(pe.z, po.z), h2pack(pe.w, po.w));
            *(uint2*)&S[cur ^ 1].Ah[ar0][acw] = a0;
            *(uint2*)&S[cur ^ 1].Ah[ar1][acw] = a1;
            *(uint4*)&S[cur ^ 1].Bh[kb][cw] = bw;
        }
        if (kt < 14) {
            int k0 = (kt + 2) * 16;
            pa0 = *(const float4*)&A[(size_t)(m0 + ar0) * 256 + k0 + ac0];
            pa1 = *(const float4*)&A[(size_t)(m0 + ar1) * 256 + k0 + ac0];
            pe  = *(const float4*)&W[(size_t)(k0 + 2 * kb) * ldw + n0 + cw];
            po  = *(const float4*)&W[(size_t)(k0 + 2 * kb + 1) * ldw + n0 + cw];
        }
        uint32_t ah[2][4];
#pragma unroll
        for (int mf = 0; mf < 2; mf++) {
            int r = wm * 32 + mf * 16 + g;
            ah[mf][0] = S[cur].Ah[r][q];
            ah[mf][1] = S[cur].Ah[r + 8][q];
            ah[mf][2] = S[cur].Ah[r][q + 4];
            ah[mf][3] = S[cur].Ah[r + 8][q + 4];
        }
#pragma unroll
        for (int u = 0; u < 8; u++) {
            int col = wn * 64 + 8 * u + g;
            uint32_t b0 = S[cur].Bh[q][col];
            uint32_t b1 = S[cur].Bh[q + 4][col];
            mma_f16(C[0][u], ah[0], b0, b1);
            mma_f16(C[1][u], ah[1], b0, b1);
        }
        __syncthreads();
    }

    const float qscale = 0.17677669529663687f * LOG2E;
    int b_ = m0 >> 10;
#pragma unroll
    for (int mf = 0; mf < 2; mf++) {
        int row = m0 + wm * 32 + mf * 16 + g;
        int n_ = row & 1023;
#pragma unroll
        for (int u = 0; u < 8; u++) {
            int col = n0 + wn * 64 + 8 * u + 2 * q;
            int seg = col >> 8;
            uint32_t* dst = (seg == 0) ? (uint32_t*)g_q
                          : ((seg == 1) ? (uint32_t*)g_k : (uint32_t*)g_v);
            int f = col & 255;
            int h = f >> 5, d = f & 31;
            size_t base = ((size_t)(b_ * HEADS + h) * NN + n_) * 16 + (d >> 1);
            float mul = (seg == 0) ? qscale : 1.0f;
            dst[base]       = h2pack(C[mf][u][0] * mul, C[mf][u][1] * mul);
            dst[base + 128] = h2pack(C[mf][u][2] * mul, C[mf][u][3] * mul);
        }
    }
}

// ---------------- kernel 3: output projection + bias (fp16 math) -------------
__global__ __launch_bounds__(256, 2) void out_tc(const float* __restrict__ W,
                                                 const float* __restrict__ bias,
                                                 float* __restrict__ out) {
    __shared__ StageH S[2];
    const int tid = threadIdx.x;
    const int lane = tid & 31, wid = tid >> 5;
    const int g = lane >> 2, q = lane & 3;
    const int wm = wid & 3, wn = wid >> 2;
    const int n0 = blockIdx.x * 128;
    const int m0 = blockIdx.y * 128;
    const int ldw = 256;

    const int ar = tid >> 1, cw4 = (tid & 1) * 4;
    const int kb = tid >> 5, cw = (tid & 31) * 4;
    const uint4* A16 = (const uint4*)g_attn16;

    float C[2][8][4] = {};
    uint4 pa;
    float4 pe, po;

    pa = A16[(size_t)(m0 + ar) * 32 + (cw4 >> 2)];
    pe = *(const float4*)&W[(size_t)(2 * kb) * ldw + n0 + cw];
    po = *(const float4*)&W[(size_t)(2 * kb + 1) * ldw + n0 + cw];
    {
        uint4 bw = make_uint4(h2pack(pe.x, po.x), h2pack(pe.y, po.y),
                              h2pack(pe.z, po.z), h2pack(pe.w, po.w));
        *(uint4*)&S[0].Ah[ar][cw4] = pa;
        *(uint4*)&S[0].Bh[kb][cw] = bw;
    }
    pa = A16[(size_t)(m0 + ar) * 32 + 2 + (cw4 >> 2)];
    pe = *(const float4*)&W[(size_t)(16 + 2 * kb) * ldw + n0 + cw];
    po = *(const float4*)&W[(size_t)(16 + 2 * kb + 1) * ldw + n0 + cw];
    __syncthreads();

    for (int kt = 0; kt < 16; kt++) {
        const int cur = kt & 1;
        if (kt < 15) {
            uint4 bw = make_uint4(h2pack(pe.x, po.x), h2pack(pe.y, po.y),
                                  h2pack(pe.z, po.z), h2pack(pe.w, po.w));
            *(uint4*)&S[cur ^ 1].Ah[ar][cw4] = pa;
            *(uint4*)&S[cur ^ 1].Bh[kb][cw] = bw;
        }
        if (kt < 14) {
            int k0 = (kt + 2) * 16;
            pa = A16[(size_t)(m0 + ar) * 32 + (k0 >> 3) + (cw4 >> 2)];
            pe = *(const float4*)&W[(size_t)(k0 + 2 * kb) * ldw + n0 + cw];
            po = *(const float4*)&W[(size_t)(k0 + 2 * kb + 1) * ldw + n0 + cw];
        }
        uint32_t ah[2][4];
#pragma unroll
        for (int mf = 0; mf < 2; mf++) {
            int r = wm * 32 + mf * 16 + g;
            ah[mf][0] = S[cur].Ah[r][q];
            ah[mf][1] = S[cur].Ah[r + 8][q];
            ah[mf][2] = S[cur].Ah[r][q + 4];
            ah[mf][3] = S[cur].Ah[r + 8][q + 4];
        }
#pragma unroll
        for (int u = 0; u < 8; u++) {
            int col = wn * 64 + 8 * u + g;
            uint32_t b0 = S[cur].Bh[q][col];
            uint32_t b1 = S[cur].Bh[q + 4][col];
            mma_f16(C[0][u], ah[0], b0, b1);
            mma_f16(C[1][u], ah[1], b0, b1);
        }
        __syncthreads();
    }

#pragma unroll
    for (int mf = 0; mf < 2; mf++) {
        int row = m0 + wm * 32 + mf * 16 + g;
#pragma unroll
        for (int u = 0; u < 8; u++) {
            int col = n0 + wn * 64 + 8 * u + 2 * q;
            float2 bv = *(const float2*)&bias[col];
            *(float2*)&out[(size_t)row * 256 + col] =
                make_float2(C[mf][u][0] + bv.x, C[mf][u][1] + bv.y);
            *(float2*)&out[(size_t)(row + 8) * 256 + col] =
                make_float2(C[mf][u][2] + bv.x, C[mf][u][3] + bv.y);
        }
    }
}

// ---------------- kernel 2: flash attention, fp16 everything -----------------
// fp16x2 exp (ex2.approx.f16x2); row-sums via ones-B mma (no shuffles at all).
__global__ __launch_bounds__(128) void attn_tc() {
    __shared__ uint32_t Qs[128][20];     // fp16x2 words: [row][d-pair]
    __shared__ uint32_t Ks[2][64][20];   // fp16x2 words: [col][d-pair]
    __shared__ uint32_t Vs[2][32][40];   // fp16x2 j-pairs: [jp][d]
    __shared__ float    Tb[TBW];         // bias table window

    const int tid = threadIdx.x;
    const int lane = tid & 31, wid = tid >> 5;
    const int g = lane >> 2, q = lane & 3;

    const int bh = blockIdx.y;
    const int h = bh & 7, b_ = bh >> 3;
    const int q0 = blockIdx.x * 128;

    const uint4* q4g = g_q + (size_t)bh * (NN * DMH / 8);
    const uint4* k4g = g_k + (size_t)bh * (NN * DMH / 8);
    const uint2* v2g = (const uint2*)(g_v + (size_t)bh * (NN * DMH / 8));
    const float* tbh = g_tbl + h * NTBL;

    const int base = ((q0 >> 5) + 31) * 63 + 31 - 1984;
    for (int j = tid; j < TBW; j += 128) {
        int idx = base + j;
        Tb[j] = tbh[idx < NTBL ? idx : NTBL - 1];
    }

#pragma unroll
    for (int i = 0; i < 4; i++) {
        int e = tid + i * 128;
        int r = e >> 2, c = e & 3;
        uint4 v = q4g[(q0 + r) * 4 + c];
        *(uint4*)&Qs[r][c * 4] = v;
    }

    const int kr = tid >> 2, kc = tid & 3;
    const int jp = tid >> 3, vc = tid & 7;

    uint4 kpre[2];
    uint2 vA[2], vB[2];
#pragma unroll
    for (int i = 0; i < 2; i++) {
        int r = kr + i * 32;
        uint4 kv = k4g[r * 4 + kc];
        *(uint4*)&Ks[0][r][kc * 4] = kv;
        int jj = jp + i * 16;
        uint2 a = v2g[(2 * jj) * 8 + vc];
        uint2 b = v2g[(2 * jj + 1) * 8 + vc];
        uint4 pw;
        pw.x = prmt(a.x, b.x, 0x5410u);
        pw.y = prmt(a.x, b.x, 0x7632u);
        pw.z = prmt(a.y, b.y, 0x5410u);
        pw.w = prmt(a.y, b.y, 0x7632u);
        *(uint4*)&Vs[0][jj][vc * 4] = pw;
    }
#pragma unroll
    for (int i = 0; i < 2; i++) {
        int r = 64 + kr + i * 32;
        kpre[i] = k4g[r * 4 + kc];
        int jj = 32 + jp + i * 16;
        vA[i] = v2g[(2 * jj) * 8 + vc];
        vB[i] = v2g[(2 * jj + 1) * 8 + vc];
    }
    __syncthreads();

    const int rb0 = wid * 32 + g;
    uint32_t qa[2][2][4];
#pragma unroll
    for (int mf = 0; mf < 2; mf++) {
        int row = rb0 + mf * 16;
#pragma unroll
        for (int ks = 0; ks < 2; ks++) {
            qa[mf][ks][0] = Qs[row][8 * ks + q];
            qa[mf][ks][1] = Qs[row + 8][8 * ks + q];
            qa[mf][ks][2] = Qs[row][8 * ks + q + 4];
            qa[mf][ks][3] = Qs[row + 8][8 * ks + q + 4];
        }
    }

    int CB[2][2];
#pragma unroll
    for (int mf = 0; mf < 2; mf++) {
        int i0 = q0 + wid * 32 + mf * 16 + g;
        int i1 = i0 + 8;
        CB[mf][0] = ((i0 >> 5) + 31) * 63 + (i0 & 31) + 31 - base;
        CB[mf][1] = ((i1 >> 5) + 31) * 63 + (i1 & 31) + 31 - base;
    }

    float O[2][4][4] = {};
    float Csum[2][4] = {};   // row-sum accumulators (ones-B mma)

    for (int kt = 0; kt < 16; kt++) {
        const int cur = kt & 1;
        __syncthreads();
        if (kt < 15) {
#pragma unroll
            for (int i = 0; i < 2; i++) {
                int r = kr + i * 32;
                *(uint4*)&Ks[cur ^ 1][r][kc * 4] = kpre[i];
                int jj = jp + i * 16;
                uint4 pw;
                pw.x = prmt(vA[i].x, vB[i].x, 0x5410u);
                pw.y = prmt(vA[i].x, vB[i].x, 0x7632u);
                pw.z = prmt(vA[i].y, vB[i].y, 0x5410u);
                pw.w = prmt(vA[i].y, vB[i].y, 0x7632u);
                *(uint4*)&Vs[cur ^ 1][jj][vc * 4] = pw;
            }
        }
        if (kt < 14) {
            int r0 = (kt + 2) * 64;
#pragma unroll
            for (int i = 0; i < 2; i++) {
                kpre[i] = k4g[(r0 + kr + i * 32) * 4 + kc];
                int jj = (kt + 2) * 32 + jp + i * 16;
                vA[i] = v2g[(2 * jj) * 8 + vc];
                vB[i] = v2g[(2 * jj + 1) * 8 + vc];
            }
        }
        const int k0 = kt * 64;

        // ---- S = bias ----
        float s[2][8][4];
#pragma unroll
        for (int mf = 0; mf < 2; mf++)
#pragma unroll
            for (int t = 0; t < 8; t++) {
                int colb = k0 + 8 * t + 2 * q;
                int off = 63 * (colb >> 5) + (colb & 31);
                s[mf][t][0] = Tb[CB[mf][0] - off];
                s[mf][t][1] = Tb[CB[mf][0] - off - 1];
                s[mf][t][2] = Tb[CB[mf][1] - off];
                s[mf][t][3] = Tb[CB[mf][1] - off - 1];
            }

        // ---- S += Q K^T ----
#pragma unroll
        for (int t = 0; t < 8; t++) {
#pragma unroll
            for (int ks = 0; ks < 2; ks++) {
                uint32_t b0 = Ks[cur][8 * t + g][8 * ks + q];
                uint32_t b1 = Ks[cur][8 * t + g][8 * ks + q + 4];
                mma_f16(s[0][t], qa[0][ks], b0, b1);
                mma_f16(s[1][t], qa[1][ks], b0, b1);
            }
        }

        // ---- pack to fp16 pairs, exp2 in fp16x2 ----
        uint32_t ph[2][8][2];
#pragma unroll
        for (int mf = 0; mf < 2; mf++)
#pragma unroll
            for (int t = 0; t < 8; t++) {
                ph[mf][t][0] = hexp2(h2pack(s[mf][t][0], s[mf][t][1]));
                ph[mf][t][1] = hexp2(h2pack(s[mf][t][2], s[mf][t][3]));
            }

        // ---- O += P V ; row-sums += P * ones ----
#pragma unroll
        for (int ks = 0; ks < 4; ks++) {
            uint32_t pa[2][4];
#pragma unroll
            for (int mf = 0; mf < 2; mf++) {
                pa[mf][0] = ph[mf][2 * ks][0];
                pa[mf][1] = ph[mf][2 * ks][1];
                pa[mf][2] = ph[mf][2 * ks + 1][0];
                pa[mf][3] = ph[mf][2 * ks + 1][1];
            }
#pragma unroll
            for (int u = 0; u < 4; u++) {
                uint32_t b0 = Vs[cur][8 * ks + q][8 * u + g];
                uint32_t b1 = Vs[cur][8 * ks + q + 4][8 * u + g];
                mma_f16(O[0][u], pa[0], b0, b1);
                mma_f16(O[1][u], pa[1], b0, b1);
            }
            mma_f16(Csum[0], pa[0], HONES, HONES);
            mma_f16(Csum[1], pa[1], HONES, HONES);
        }
    }

    // ---- epilogue: l fully reduced by ones-mma; normalize, write fp16 ----
#pragma unroll
    for (int mf = 0; mf < 2; mf++) {
        float inv0 = 1.0f / Csum[mf][0];
        float inv1 = 1.0f / Csum[mf][2];
        int orow = q0 + wid * 32 + mf * 16 + g;
#pragma unroll
        for (int u = 0; u < 4; u++) {
            int dw = h * 16 + 4 * u + q;
            g_attn16[((size_t)b_ * NN + orow) * 128 + dw] =
                h2pack(O[mf][u][0] * inv0, O[mf][u][1] * inv0);
            g_attn16[((size_t)b_ * NN + orow + 8) * 128 + dw] =
                h2pack(O[mf][u][2] * inv1, O[mf][u][3] * inv1);
        }
    }
}

// ---------------- launch ----------------
extern "C" void kernel_launch(void* const* d_in, const int* in_sizes, int n_in,
                              void* d_out, int out_size) {
    const float* x      = (const float*)d_in[0];
    const float* w_qkv  = (const float*)d_in[1];
    const float* w_out  = (const float*)d_in[2];
    const float* b_out  = (const float*)d_in[3];
    const float* table  = (const float*)d_in[4];
    float* out = (float*)d_out;

    tbl_kernel<<<(NTBL * HEADS + 255) / 256, 256>>>(table);
    qkv_tc<<<dim3(768 / 128, (BB * NN) / 128), 256>>>(x, w_qkv);
    attn_tc<<<dim3(NN / 128, BB * HEADS), 128>>>();
    out_tc<<<dim3(256 / 128, (BB * NN) / 128), 256>>>(w_out, b_out, out);
}

// round 16
// speedup vs baseline: 1.6603x; 1.0072x over previous
#include <cuda_runtime.h>
#include <cuda_fp16.h>
#include <cstdint>

#define BB 16
#define NN 1024
#define INP 256
#define HEADS 8
#define DMH 32
#define INNER 256
#define OUP 256
#define NTBL 3969   // (2*32-1)^2
#define LOG2E 1.4426950408889634f
#define TBW 2208    // bias table window per CTA
#define HONES 0x3C003C00u
#define NW1 (128 * 768)   // w_qkv kpair words
#define NW2 (128 * 256)   // w_out kpair words
#define NTT (NTBL * 8)    // table entries

// ---------------- device scratch (allocation-free) ----------------
__device__ uint4 g_q[BB * HEADS * NN * DMH / 8];      // fp16, scale*log2e folded
__device__ uint4 g_k[BB * HEADS * NN * DMH / 8];      // fp16
__device__ uint4 g_v[BB * HEADS * NN * DMH / 8];      // fp16
__device__ uint32_t g_attn16[BB * NN * (INNER / 2)];  // fp16 pairs (b, n, d/2)
__device__ float g_tbl[HEADS * NTBL];                 // [h][idx], *log2e
__device__ uint4 g_x16[BB * NN * INP / 8];            // x as fp16 pairs
__device__ uint32_t g_wq16[NW1];                      // w_qkv kpair-interleaved fp16
__device__ uint32_t g_wo16[NW2];                      // w_out  kpair-interleaved fp16

// ---------------- helpers ----------------
__device__ __forceinline__ uint32_t h2pack(float lo, float hi) {
    uint32_t r;
    asm("cvt.rn.f16x2.f32 %0, %1, %2;" : "=r"(r) : "f"(hi), "f"(lo));
    return r;
}

__device__ __forceinline__ uint32_t hexp2(uint32_t x) {
    uint32_t r;
    asm("ex2.approx.f16x2 %0, %1;" : "=r"(r) : "r"(x));
    return r;
}

__device__ __forceinline__ uint32_t prmt(uint32_t a, uint32_t b, uint32_t sel) {
    uint32_t d;
    asm("prmt.b32 %0, %1, %2, %3;" : "=r"(d) : "r"(a), "r"(b), "r"(sel));
    return d;
}

__device__ __forceinline__ void mma_f16(float c[4], const uint32_t a[4],
                                        uint32_t b0, uint32_t b1) {
    asm volatile(
        "mma.sync.aligned.m16n8k16.row.col.f32.f16.f16.f32 "
        "{%0,%1,%2,%3}, {%4,%5,%6,%7}, {%8,%9}, {%0,%1,%2,%3};"
        : "+f"(c[0]), "+f"(c[1]), "+f"(c[2]), "+f"(c[3])
        : "r"(a[0]), "r"(a[1]), "r"(a[2]), "r"(a[3]), "r"(b0), "r"(b1));
}

// ---------------- kernel 0a: convert x to fp16 pairs -------------------------
__global__ __launch_bounds__(256) void cvt_x(const float* __restrict__ x) {
    int t = blockIdx.x * 256 + threadIdx.x;       // 0 .. 524287
    const float4* x4 = (const float4*)x;
    float4 a = x4[2 * t], b = x4[2 * t + 1];
    uint4 w = make_uint4(h2pack(a.x, a.y), h2pack(a.z, a.w),
                         h2pack(b.x, b.y), h2pack(b.z, b.w));
    g_x16[t] = w;
}

// ---------------- kernel 0b: weights -> kpair-interleaved fp16; bias table ---
__global__ __launch_bounds__(256) void cvt_wt(const float* __restrict__ wq,
                                              const float* __restrict__ wo,
                                              const float* __restrict__ table) {
    int t = blockIdx.x * 256 + threadIdx.x;
    if (t < NW1) {
        int kp = t / 768, n = t - kp * 768;
        g_wq16[t] = h2pack(wq[(2 * kp) * 768 + n], wq[(2 * kp + 1) * 768 + n]);
        return;
    }
    t -= NW1;
    if (t < NW2) {
        int kp = t >> 8, n = t & 255;
        g_wo16[t] = h2pack(wo[(2 * kp) * 256 + n], wo[(2 * kp + 1) * 256 + n]);
        return;
    }
    t -= NW2;
    if (t < NTT) {
        int idx = t >> 3, h = t & 7;
        g_tbl[h * NTBL + idx] = table[t] * LOG2E;
    }
}

// ========= fp16 m16n8k16 GEMM core, 128x128 tile, K-step 16, raw uint4 fills ==
#define PAH 12
#define PBH 136

struct StageH {
    uint32_t Ah[128][PAH];
    uint32_t Bh[8][PBH];
};

// ---------------- kernel 1: QKV GEMM ----------------
__global__ __launch_bounds__(256, 2) void qkv_tc() {
    __shared__ StageH S[2];
    const int tid = threadIdx.x;
    const int lane = tid & 31, wid = tid >> 5;
    const int g = lane >> 2, q = lane & 3;
    const int wm = wid & 3, wn = wid >> 2;
    const int n0 = blockIdx.x * 128;
    const int m0 = blockIdx.y * 128;

    const int ar = tid >> 1, asel = tid & 1;      // A: 1 uint4/thread/tile
    const int kb = tid >> 5, cwu = tid & 31;      // B: 1 uint4/thread/tile
    const uint4* A16 = g_x16;                     // row = 32 uint4
    const uint4* B16 = (const uint4*)g_wq16;      // kpair row = 192 uint4
    const int bcol = (n0 >> 2) + cwu;

    float C[2][8][4] = {};
    uint4 pa, pb;

    pa = A16[(size_t)(m0 + ar) * 32 + asel];
    pb = B16[(size_t)kb * 192 + bcol];
    *(uint4*)&S[0].Ah[ar][asel * 4] = pa;
    *(uint4*)&S[0].Bh[kb][cwu * 4] = pb;
    pa = A16[(size_t)(m0 + ar) * 32 + 2 + asel];
    pb = B16[(size_t)(8 + kb) * 192 + bcol];
    __syncthreads();

    for (int kt = 0; kt < 16; kt++) {
        const int cur = kt & 1;
        if (kt < 15) {
            *(uint4*)&S[cur ^ 1].Ah[ar][asel * 4] = pa;
            *(uint4*)&S[cur ^ 1].Bh[kb][cwu * 4] = pb;
        }
        if (kt < 14) {
            pa = A16[(size_t)(m0 + ar) * 32 + (kt + 2) * 2 + asel];
            pb = B16[(size_t)((kt + 2) * 8 + kb) * 192 + bcol];
        }
        uint32_t ah[2][4];
#pragma unroll
        for (int mf = 0; mf < 2; mf++) {
            int r = wm * 32 + mf * 16 + g;
            ah[mf][0] = S[cur].Ah[r][q];
            ah[mf][1] = S[cur].Ah[r + 8][q];
            ah[mf][2] = S[cur].Ah[r][q + 4];
            ah[mf][3] = S[cur].Ah[r + 8][q + 4];
        }
#pragma unroll
        for (int u = 0; u < 8; u++) {
            int col = wn * 64 + 8 * u + g;
            uint32_t b0 = S[cur].Bh[q][col];
            uint32_t b1 = S[cur].Bh[q + 4][col];
            mma_f16(C[0][u], ah[0], b0, b1);
            mma_f16(C[1][u], ah[1], b0, b1);
        }
        __syncthreads();
    }

    const float qscale = 0.17677669529663687f * LOG2E;
    int b_ = m0 >> 10;
#pragma unroll
    for (int mf = 0; mf < 2; mf++) {
        int row = m0 + wm * 32 + mf * 16 + g;
        int n_ = row & 1023;
#pragma unroll
        for (int u = 0; u < 8; u++) {
            int col = n0 + wn * 64 + 8 * u + 2 * q;
            int seg = col >> 8;
            uint32_t* dst = (seg == 0) ? (uint32_t*)g_q
                          : ((seg == 1) ? (uint32_t*)g_k : (uint32_t*)g_v);
            int f = col & 255;
            int h = f >> 5, d = f & 31;
            size_t base = ((size_t)(b_ * HEADS + h) * NN + n_) * 16 + (d >> 1);
            float mul = (seg == 0) ? qscale : 1.0f;
            dst[base]       = h2pack(C[mf][u][0] * mul, C[mf][u][1] * mul);
            dst[base + 128] = h2pack(C[mf][u][2] * mul, C[mf][u][3] * mul);
        }
    }
}

// ---------------- kernel 3: output projection + bias -------------------------
__global__ __launch_bounds__(256, 2) void out_tc(const float* __restrict__ bias,
                                                 float* __restrict__ out) {
    __shared__ StageH S[2];
    const int tid = threadIdx.x;
    const int lane = tid & 31, wid = tid >> 5;
    const int g = lane >> 2, q = lane & 3;
    const int wm = wid & 3, wn = wid >> 2;
    const int n0 = blockIdx.x * 128;
    const int m0 = blockIdx.y * 128;

    const int ar = tid >> 1, asel = tid & 1;
    const int kb = tid >> 5, cwu = tid & 31;
    const uint4* A16 = (const uint4*)g_attn16;    // row = 32 uint4
    const uint4* B16 = (const uint4*)g_wo16;      // kpair row = 64 uint4
    const int bcol = (n0 >> 2) + cwu;

    float C[2][8][4] = {};
    uint4 pa, pb;

    pa = A16[(size_t)(m0 + ar) * 32 + asel];
    pb = B16[(size_t)kb * 64 + bcol];
    *(uint4*)&S[0].Ah[ar][asel * 4] = pa;
    *(uint4*)&S[0].Bh[kb][cwu * 4] = pb;
    pa = A16[(size_t)(m0 + ar) * 32 + 2 + asel];
    pb = B16[(size_t)(8 + kb) * 64 + bcol];
    __syncthreads();

    for (int kt = 0; kt < 16; kt++) {
        const int cur = kt & 1;
        if (kt < 15) {
            *(uint4*)&S[cur ^ 1].Ah[ar][asel * 4] = pa;
            *(uint4*)&S[cur ^ 1].Bh[kb][cwu * 4] = pb;
        }
        if (kt < 14) {
            pa = A16[(size_t)(m0 + ar) * 32 + (kt + 2) * 2 + asel];
            pb = B16[(size_t)((kt + 2) * 8 + kb) * 64 + bcol];
        }
        uint32_t ah[2][4];
#pragma unroll
        for (int mf = 0; mf < 2; mf++) {
            int r = wm * 32 + mf * 16 + g;
            ah[mf][0] = S[cur].Ah[r][q];
            ah[mf][1] = S[cur].Ah[r + 8][q];
            ah[mf][2] = S[cur].Ah[r][q + 4];
            ah[mf][3] = S[cur].Ah[r + 8][q + 4];
        }
#pragma unroll
        for (int u = 0; u < 8; u++) {
            int col = wn * 64 + 8 * u + g;
            uint32_t b0 = S[cur].Bh[q][col];
            uint32_t b1 = S[cur].Bh[q + 4][col];
            mma_f16(C[0][u], ah[0], b0, b1);
            mma_f16(C[1][u], ah[1], b0, b1);
        }
        __syncthreads();
    }

#pragma unroll
    for (int mf = 0; mf < 2; mf++) {
        int row = m0 + wm * 32 + mf * 16 + g;
#pragma unroll
        for (int u = 0; u < 8; u++) {
            int col = n0 + wn * 64 + 8 * u + 2 * q;
            float2 bv = *(const float2*)&bias[col];
            *(float2*)&out[(size_t)row * 256 + col] =
                make_float2(C[mf][u][0] + bv.x, C[mf][u][1] + bv.y);
            *(float2*)&out[(size_t)(row + 8) * 256 + col] =
                make_float2(C[mf][u][2] + bv.x, C[mf][u][3] + bv.y);
        }
    }
}

// ---------------- kernel 2: flash attention, fp16 everything -----------------
__global__ __launch_bounds__(128) void attn_tc() {
    __shared__ uint32_t Qs[128][20];     // fp16x2 words: [row][d-pair]
    __shared__ uint32_t Ks[2][64][20];   // fp16x2 words: [col][d-pair]
    __shared__ uint32_t Vs[2][32][40];   // fp16x2 j-pairs: [jp][d]
    __shared__ float    Tb[TBW];         // bias table window

    const int tid = threadIdx.x;
    const int lane = tid & 31, wid = tid >> 5;
    const int g = lane >> 2, q = lane & 3;

    const int bh = blockIdx.y;
    const int h = bh & 7, b_ = bh >> 3;
    const int q0 = blockIdx.x * 128;

    const uint4* q4g = g_q + (size_t)bh * (NN * DMH / 8);
    const uint4* k4g = g_k + (size_t)bh * (NN * DMH / 8);
    const uint2* v2g = (const uint2*)(g_v + (size_t)bh * (NN * DMH / 8));
    const float* tbh = g_tbl + h * NTBL;

    const int base = ((q0 >> 5) + 31) * 63 + 31 - 1984;
    for (int j = tid; j < TBW; j += 128) {
        int idx = base + j;
        Tb[j] = tbh[idx < NTBL ? idx : NTBL - 1];
    }

#pragma unroll
    for (int i = 0; i < 4; i++) {
        int e = tid + i * 128;
        int r = e >> 2, c = e & 3;
        uint4 v = q4g[(q0 + r) * 4 + c];
        *(uint4*)&Qs[r][c * 4] = v;
    }

    const int kr = tid >> 2, kc = tid & 3;
    const int jp = tid >> 3, vc = tid & 7;

    uint4 kpre[2];
    uint2 vA[2], vB[2];
#pragma unroll
    for (int i = 0; i < 2; i++) {
        int r = kr + i * 32;
        uint4 kv = k4g[r * 4 + kc];
        *(uint4*)&Ks[0][r][kc * 4] = kv;
        int jj = jp + i * 16;
        uint2 a = v2g[(2 * jj) * 8 + vc];
        uint2 b = v2g[(2 * jj + 1) * 8 + vc];
        uint4 pw;
        pw.x = prmt(a.x, b.x, 0x5410u);
        pw.y = prmt(a.x, b.x, 0x7632u);
        pw.z = prmt(a.y, b.y, 0x5410u);
        pw.w = prmt(a.y, b.y, 0x7632u);
        *(uint4*)&Vs[0][jj][vc * 4] = pw;
    }
#pragma unroll
    for (int i = 0; i < 2; i++) {
        int r = 64 + kr + i * 32;
        kpre[i] = k4g[r * 4 + kc];
        int jj = 32 + jp + i * 16;
        vA[i] = v2g[(2 * jj) * 8 + vc];
        vB[i] = v2g[(2 * jj + 1) * 8 + vc];
    }
    __syncthreads();

    const int rb0 = wid * 32 + g;
    uint32_t qa[2][2][4];
#pragma unroll
    for (int mf = 0; mf < 2; mf++) {
        int row = rb0 + mf * 16;
#pragma unroll
        for (int ks = 0; ks < 2; ks++) {
            qa[mf][ks][0] = Qs[row][8 * ks + q];
            qa[mf][ks][1] = Qs[row + 8][8 * ks + q];
            qa[mf][ks][2] = Qs[row][8 * ks + q + 4];
            qa[mf][ks][3] = Qs[row + 8][8 * ks + q + 4];
        }
    }

    int CB[2][2];
#pragma unroll
    for (int mf = 0; mf < 2; mf++) {
        int i0 = q0 + wid * 32 + mf * 16 + g;
        int i1 = i0 + 8;
        CB[mf][0] = ((i0 >> 5) + 31) * 63 + (i0 & 31) + 31 - base;
        CB[mf][1] = ((i1 >> 5) + 31) * 63 + (i1 & 31) + 31 - base;
    }

    float O[2][4][4] = {};
    float Csum[2][4] = {};

    for (int kt = 0; kt < 16; kt++) {
        const int cur = kt & 1;
        __syncthreads();
        if (kt < 15) {
#pragma unroll
            for (int i = 0; i < 2; i++) {
                int r = kr + i * 32;
                *(uint4*)&Ks[cur ^ 1][r][kc * 4] = kpre[i];
                int jj = jp + i * 16;
                uint4 pw;
                pw.x = prmt(vA[i].x, vB[i].x, 0x5410u);
                pw.y = prmt(vA[i].x, vB[i].x, 0x7632u);
                pw.z = prmt(vA[i].y, vB[i].y, 0x5410u);
                pw.w = prmt(vA[i].y, vB[i].y, 0x7632u);
                *(uint4*)&Vs[cur ^ 1][jj][vc * 4] = pw;
            }
        }
        if (kt < 14) {
            int r0 = (kt + 2) * 64;
#pragma unroll
            for (int i = 0; i < 2; i++) {
                kpre[i] = k4g[(r0 + kr + i * 32) * 4 + kc];
                int jj = (kt + 2) * 32 + jp + i * 16;
                vA[i] = v2g[(2 * jj) * 8 + vc];
                vB[i] = v2g[(2 * jj + 1) * 8 + vc];
            }
        }
        const int k0 = kt * 64;

        // ---- S = bias ----
        float s[2][8][4];
#pragma unroll
        for (int mf = 0; mf < 2; mf++)
#pragma unroll
            for (int t = 0; t < 8; t++) {
                int colb = k0 + 8 * t + 2 * q;
                int off = 63 * (colb >> 5) + (colb & 31);
                s[mf][t][0] = Tb[CB[mf][0] - off];
                s[mf][t][1] = Tb[CB[mf][0] - off - 1];
                s[mf][t][2] = Tb[CB[mf][1] - off];
                s[mf][t][3] = Tb[CB[mf][1] - off - 1];
            }

        // ---- S += Q K^T ----
#pragma unroll
        for (int t = 0; t < 8; t++) {
#pragma unroll
            for (int ks = 0; ks < 2; ks++) {
                uint32_t b0 = Ks[cur][8 * t + g][8 * ks + q];
                uint32_t b1 = Ks[cur][8 * t + g][8 * ks + q + 4];
                mma_f16(s[0][t], qa[0][ks], b0, b1);
                mma_f16(s[1][t], qa[1][ks], b0, b1);
            }
        }

        // ---- pack to fp16 pairs, exp2 in fp16x2 ----
        uint32_t ph[2][8][2];
#pragma unroll
        for (int mf = 0; mf < 2; mf++)
#pragma unroll
            for (int t = 0; t < 8; t++) {
                ph[mf][t][0] = hexp2(h2pack(s[mf][t][0], s[mf][t][1]));
                ph[mf][t][1] = hexp2(h2pack(s[mf][t][2], s[mf][t][3]));
            }

        // ---- O += P V ; row-sums += P * ones ----
#pragma unroll
        for (int ks = 0; ks < 4; ks++) {
            uint32_t pa[2][4];
#pragma unroll
            for (int mf = 0; mf < 2; mf++) {
                pa[mf][0] = ph[mf][2 * ks][0];
                pa[mf][1] = ph[mf][2 * ks][1];
                pa[mf][2] = ph[mf][2 * ks + 1][0];
                pa[mf][3] = ph[mf][2 * ks + 1][1];
            }
#pragma unroll
            for (int u = 0; u < 4; u++) {
                uint32_t b0 = Vs[cur][8 * ks + q][8 * u + g];
                uint32_t b1 = Vs[cur][8 * ks + q + 4][8 * u + g];
                mma_f16(O[0][u], pa[0], b0, b1);
                mma_f16(O[1][u], pa[1], b0, b1);
            }
            mma_f16(Csum[0], pa[0], HONES, HONES);
            mma_f16(Csum[1], pa[1], HONES, HONES);
        }
    }

    // ---- epilogue: normalize, write fp16 ----
#pragma unroll
    for (int mf = 0; mf < 2; mf++) {
        float inv0 = 1.0f / Csum[mf][0];
        float inv1 = 1.0f / Csum[mf][2];
        int orow = q0 + wid * 32 + mf * 16 + g;
#pragma unroll
        for (int u = 0; u < 4; u++) {
            int dw = h * 16 + 4 * u + q;
            g_attn16[((size_t)b_ * NN + orow) * 128 + dw] =
                h2pack(O[mf][u][0] * inv0, O[mf][u][1] * inv0);
            g_attn16[((size_t)b_ * NN + orow + 8) * 128 + dw] =
                h2pack(O[mf][u][2] * inv1, O[mf][u][3] * inv1);
        }
    }
}

// ---------------- launch ----------------
extern "C" void kernel_launch(void* const* d_in, const int* in_sizes, int n_in,
                              void* d_out, int out_size) {
    const float* x      = (const float*)d_in[0];
    const float* w_qkv  = (const float*)d_in[1];
    const float* w_out  = (const float*)d_in[2];
    const float* b_out  = (const float*)d_in[3];
    const float* table  = (const float*)d_in[4];
    float* out = (float*)d_out;

    cvt_x<<<(BB * NN * INP / 8) / 256, 256>>>(x);
    cvt_wt<<<(NW1 + NW2 + NTT + 255) / 256, 256>>>(w_qkv, w_out, table);
    qkv_tc<<<dim3(768 / 128, (BB * NN) / 128), 256>>>();
    attn_tc<<<dim3(NN / 128, BB * HEADS), 128>>>();
    out_tc<<<dim3(256 / 128, (BB * NN) / 128), 256>>>(b_out, out);
}